// round 2
// baseline (speedup 1.0000x reference)
#include <cuda_runtime.h>
#include <math.h>
#include <limits.h>

// Problem shape (fixed by the dataset)
#define B_      64
#define TOK     50
#define P_PER_B 49
#define NP      (B_ * P_PER_B)   // 3136 patches
#define D_      768
#define NM      100000

// GEMM tiling
#define BM 128
#define BN 128
#define BK 16
#define TM 8
#define TN 8
#define NTHREADS 256

// ---------------- scratch (device globals: allocation-guard safe) ----------
__device__ float g_patches[NP * D_];   // normalized patches, row-major [3136][768]
__device__ float g_p2[NP];             // ||p_norm||^2 per patch
__device__ float g_inv[NM];            // 1/(||m||+eps)
__device__ float g_half_m2[NM];        // 0.5 * ||m_norm||^2
__device__ int   g_maxv[NP];           // ordered-int encoded max_m(dot*inv - half_m2)

// ordered-int encoding: monotone float<->int so atomicMax(int) works
__device__ __forceinline__ int f2ord(float f) {
    int i = __float_as_int(f);
    return (i >= 0) ? i : (i ^ 0x7FFFFFFF);
}
__device__ __forceinline__ float ord2f(int i) {
    return __int_as_float((i >= 0) ? i : (i ^ 0x7FFFFFFF));
}

// ---------------- kernel 1: normalize patch tokens -------------------------
__global__ void norm_patches_kernel(const float* __restrict__ tokens) {
    int pb = blockIdx.x;                   // 0..3135
    int b  = pb / P_PER_B;
    int j  = pb % P_PER_B;
    const float* src = tokens + ((size_t)(b * TOK + 1 + j)) * D_;
    float* dst = g_patches + (size_t)pb * D_;

    int tid = threadIdx.x;                 // 256 threads, 3 elems each
    float v0 = src[tid];
    float v1 = src[tid + 256];
    float v2 = src[tid + 512];
    float s = v0 * v0 + v1 * v1 + v2 * v2;

    __shared__ float ws[8];
    __shared__ float s_tot;
    #pragma unroll
    for (int o = 16; o; o >>= 1) s += __shfl_xor_sync(0xFFFFFFFFu, s, o);
    if ((tid & 31) == 0) ws[tid >> 5] = s;
    __syncthreads();
    if (tid < 32) {
        float t = (tid < 8) ? ws[tid] : 0.0f;
        #pragma unroll
        for (int o = 4; o; o >>= 1) t += __shfl_xor_sync(0xFFFFFFFFu, t, o);
        if (tid == 0) s_tot = t;
    }
    __syncthreads();
    float tot = s_tot;
    float inv = 1.0f / (sqrtf(tot) + 1e-12f);
    dst[tid]       = v0 * inv;
    dst[tid + 256] = v1 * inv;
    dst[tid + 512] = v2 * inv;
    if (tid == 0) g_p2[pb] = tot * inv * inv;
}

// ---------------- kernel 2: memory-bank row stats ---------------------------
__global__ void mb_stats_kernel(const float* __restrict__ mb) {
    int row  = blockIdx.x * 8 + (threadIdx.x >> 5);
    int lane = threadIdx.x & 31;
    if (row >= NM) return;
    const float4* r = (const float4*)(mb + (size_t)row * D_);
    float s = 0.0f;
    #pragma unroll
    for (int i = 0; i < 6; i++) {
        float4 v = r[lane + i * 32];       // 192 float4 per row
        s += v.x * v.x + v.y * v.y + v.z * v.z + v.w * v.w;
    }
    #pragma unroll
    for (int o = 16; o; o >>= 1) s += __shfl_xor_sync(0xFFFFFFFFu, s, o);
    if (lane == 0) {
        float inv = 1.0f / (sqrtf(s) + 1e-12f);
        g_inv[row]     = inv;
        g_half_m2[row] = 0.5f * s * inv * inv;
    }
}

// ---------------- kernel 3: init per-patch max -------------------------------
__global__ void init_max_kernel() {
    int i = blockIdx.x * blockDim.x + threadIdx.x;
    if (i < NP) g_maxv[i] = INT_MIN;
}

// ---------------- kernel 4: GEMM + max epilogue ------------------------------
__global__ void __launch_bounds__(NTHREADS, 2)
gemm_max_kernel(const float* __restrict__ mb) {
    __shared__ __align__(16) float As[BK][BM];
    __shared__ __align__(16) float Bs[BK][BN];
    __shared__ float red[BM][17];          // padded to dodge bank conflicts

    const int mtile = blockIdx.x;
    const int ptile = blockIdx.y;
    const int p0 = ptile * BM;
    const int m0 = mtile * BN;
    const int tid = threadIdx.x;
    const int tx = tid & 15;
    const int ty = tid >> 4;

    float acc[TM][TN];
    #pragma unroll
    for (int i = 0; i < TM; i++)
        #pragma unroll
        for (int j = 0; j < TN; j++) acc[i][j] = 0.0f;

    for (int k0 = 0; k0 < D_; k0 += BK) {
        // load tiles: 128 rows x 16 cols = 512 float4 per operand
        #pragma unroll
        for (int it = 0; it < 2; it++) {
            int idx = it * NTHREADS + tid;
            int row = idx >> 2;
            int c4  = (idx & 3) << 2;
            int gp = p0 + row;
            float4 va = (gp < NP)
                ? *(const float4*)&g_patches[(size_t)gp * D_ + k0 + c4]
                : make_float4(0.f, 0.f, 0.f, 0.f);
            As[c4 + 0][row] = va.x; As[c4 + 1][row] = va.y;
            As[c4 + 2][row] = va.z; As[c4 + 3][row] = va.w;
            int gm = m0 + row;
            float4 vb = (gm < NM)
                ? *(const float4*)&mb[(size_t)gm * D_ + k0 + c4]
                : make_float4(0.f, 0.f, 0.f, 0.f);
            Bs[c4 + 0][row] = vb.x; Bs[c4 + 1][row] = vb.y;
            Bs[c4 + 2][row] = vb.z; Bs[c4 + 3][row] = vb.w;
        }
        __syncthreads();

        #pragma unroll
        for (int k = 0; k < BK; k++) {
            float4 a0 = *(const float4*)&As[k][ty * TM];
            float4 a1 = *(const float4*)&As[k][ty * TM + 4];
            float4 b0 = *(const float4*)&Bs[k][tx * TN];
            float4 b1 = *(const float4*)&Bs[k][tx * TN + 4];
            float ra[TM] = {a0.x, a0.y, a0.z, a0.w, a1.x, a1.y, a1.z, a1.w};
            float rb[TN] = {b0.x, b0.y, b0.z, b0.w, b1.x, b1.y, b1.z, b1.w};
            #pragma unroll
            for (int i = 0; i < TM; i++)
                #pragma unroll
                for (int j = 0; j < TN; j++)
                    acc[i][j] = fmaf(ra[i], rb[j], acc[i][j]);
        }
        __syncthreads();
    }

    // epilogue: v = dot*inv_m - half_m2[m]; per-thread max over its 8 columns
    float inv[TN], bias[TN];
    #pragma unroll
    for (int j = 0; j < TN; j++) {
        int m = m0 + tx * TN + j;
        bool ok = (m < NM);
        inv[j]  = ok ? g_inv[m]     : 0.0f;
        bias[j] = ok ? g_half_m2[m] : 1e30f;  // invalid column can never win
    }
    #pragma unroll
    for (int i = 0; i < TM; i++) {
        float best = -3.0e38f;
        #pragma unroll
        for (int j = 0; j < TN; j++) {
            float v = acc[i][j] * inv[j] - bias[j];
            best = fmaxf(best, v);
        }
        red[ty * TM + i][tx] = best;
    }
    __syncthreads();

    if (tid < BM) {
        int p = p0 + tid;
        if (p < NP) {
            float best = red[tid][0];
            #pragma unroll
            for (int t = 1; t < 16; t++) best = fmaxf(best, red[tid][t]);
            atomicMax(&g_maxv[p], f2ord(best));
        }
    }
}

// ---------------- kernel 5: finalize per-image score -------------------------
__global__ void finalize_kernel(float* __restrict__ out) {
    int b = threadIdx.x;
    if (b >= B_) return;
    float mx = -3.0e38f;
    #pragma unroll 7
    for (int j = 0; j < P_PER_B; j++) {
        int p = b * P_PER_B + j;
        float v  = ord2f(g_maxv[p]);
        float d2 = g_p2[p] - 2.0f * v;      // min_m squared distance for patch p
        mx = fmaxf(mx, d2);
    }
    out[b] = sqrtf(fmaxf(mx, 1e-12f));
}

// ---------------- launch ------------------------------------------------------
extern "C" void kernel_launch(void* const* d_in, const int* in_sizes, int n_in,
                              void* d_out, int out_size) {
    (void)in_sizes; (void)n_in; (void)out_size;
    const float* tokens = (const float*)d_in[0];
    const float* mb     = (const float*)d_in[1];
    float* out          = (float*)d_out;

    norm_patches_kernel<<<NP, 256>>>(tokens);
    mb_stats_kernel<<<(NM + 7) / 8, 256>>>(mb);
    init_max_kernel<<<(NP + 255) / 256, 256>>>();

    dim3 grid((NM + BN - 1) / BN, (NP + BM - 1) / BM);  // 782 x 25
    gemm_max_kernel<<<grid, NTHREADS>>>(mb);

    finalize_kernel<<<1, 64>>>(out);
}

// round 4
// speedup vs baseline: 10.3450x; 10.3450x over previous
#include <cuda_runtime.h>
#include <cuda_bf16.h>
#include <math.h>
#include <limits.h>
#include <stdint.h>

// ---------------- problem shape ----------------
#define B_      64
#define TOK     50
#define P_PER_B 49
#define NP      3136
#define NP_PAD  3200      // 25 * 128
#define D_      768
#define NM      100000
#define NM_PAD  100096    // 782 * 128

// ---------------- GEMM tiling ------------------
#define BM 128            // patches per CTA
#define BN 128            // mb rows per CTA
#define KC 64             // K per chunk
#define NCHUNK (D_ / KC)  // 12
#define NTHR 256          // 8 warps: 2 (M) x 4 (N), warp tile 64x32

// SMEM layout (dynamic)
#define SM_A0   0
#define SM_A1   16384
#define SM_B0   32768
#define SM_B1   49152
#define SM_INV  65536
#define SM_BIAS (65536 + 512)
#define SM_RED  (65536 + 1024)              // 128*4 floats
#define SM_TOTAL (65536 + 1024 + 2048)      // 68608 B

// ---------------- scratch (device globals) -----
__device__ __nv_bfloat16 g_pA[(size_t)NP_PAD * D_];
__device__ __nv_bfloat16 g_mbB[(size_t)NM_PAD * D_];
__device__ float g_p2[NP];
__device__ float g_inv[NM_PAD];
__device__ float g_bias[NM_PAD];     // 0.5*||m_norm||^2 (1e30 for padding)
__device__ int   g_maxv[NP];

// ---------------- helpers ----------------------
__device__ __forceinline__ int f2ord(float f) {
    int i = __float_as_int(f);
    return (i >= 0) ? i : (i ^ 0x7FFFFFFF);
}
__device__ __forceinline__ float ord2f(int i) {
    return __int_as_float((i >= 0) ? i : (i ^ 0x7FFFFFFF));
}
__device__ __forceinline__ uint32_t smem_u32(const void* p) {
    uint32_t a;
    asm("{ .reg .u64 t; cvta.to.shared.u64 t, %1; cvt.u32.u64 %0, t; }" : "=r"(a) : "l"(p));
    return a;
}
__device__ __forceinline__ void cp_async16(uint32_t dst, const void* src) {
    asm volatile("cp.async.cg.shared.global [%0], [%1], 16;" :: "r"(dst), "l"(src));
}
#define CP_COMMIT() asm volatile("cp.async.commit_group;" ::: "memory")
#define CP_WAIT0()  asm volatile("cp.async.wait_group 0;" ::: "memory")
#define CP_WAIT1()  asm volatile("cp.async.wait_group 1;" ::: "memory")

__device__ __forceinline__ uint32_t sw128(uint32_t off) {
    return off ^ ((off >> 3) & 0x70);
}
__device__ __forceinline__ void ldmat_x4(uint32_t* r, uint32_t addr) {
    asm volatile("ldmatrix.sync.aligned.m8n8.x4.shared.b16 {%0,%1,%2,%3}, [%4];"
        : "=r"(r[0]), "=r"(r[1]), "=r"(r[2]), "=r"(r[3]) : "r"(addr));
}
__device__ __forceinline__ void mma16816(float* c, const uint32_t* a, const uint32_t* b) {
    asm volatile(
        "mma.sync.aligned.m16n8k16.row.col.f32.bf16.bf16.f32 "
        "{%0,%1,%2,%3}, {%4,%5,%6,%7}, {%8,%9}, {%0,%1,%2,%3};"
        : "+f"(c[0]), "+f"(c[1]), "+f"(c[2]), "+f"(c[3])
        : "r"(a[0]), "r"(a[1]), "r"(a[2]), "r"(a[3]), "r"(b[0]), "r"(b[1]));
}

// ---------------- kernel 1: normalize patches -> bf16 ----------------------
__global__ void norm_patches_kernel(const float* __restrict__ tokens) {
    int pb = blockIdx.x;
    int tid = threadIdx.x;
    __nv_bfloat16* dst = g_pA + (size_t)pb * D_;
    if (pb >= NP) {
        dst[tid] = __float2bfloat16(0.f);
        dst[tid + 256] = __float2bfloat16(0.f);
        dst[tid + 512] = __float2bfloat16(0.f);
        return;
    }
    int b = pb / P_PER_B, j = pb % P_PER_B;
    const float* src = tokens + ((size_t)(b * TOK + 1 + j)) * D_;
    float v0 = src[tid], v1 = src[tid + 256], v2 = src[tid + 512];
    float s = v0 * v0 + v1 * v1 + v2 * v2;

    __shared__ float ws[8];
    __shared__ float s_tot;
    #pragma unroll
    for (int o = 16; o; o >>= 1) s += __shfl_xor_sync(0xFFFFFFFFu, s, o);
    if ((tid & 31) == 0) ws[tid >> 5] = s;
    __syncthreads();
    if (tid < 32) {
        float t = (tid < 8) ? ws[tid] : 0.0f;
        #pragma unroll
        for (int o = 4; o; o >>= 1) t += __shfl_xor_sync(0xFFFFFFFFu, t, o);
        if (tid == 0) s_tot = t;
    }
    __syncthreads();
    float tot = s_tot;
    float inv = 1.0f / (sqrtf(tot) + 1e-12f);
    dst[tid]       = __float2bfloat16(v0 * inv);
    dst[tid + 256] = __float2bfloat16(v1 * inv);
    dst[tid + 512] = __float2bfloat16(v2 * inv);
    if (tid == 0) g_p2[pb] = tot * inv * inv;
}

// ---------------- kernel 2: MB stats + fp32->bf16 convert ------------------
__global__ void mb_convert_kernel(const float* __restrict__ mb) {
    int row  = blockIdx.x * 8 + (threadIdx.x >> 5);
    int lane = threadIdx.x & 31;
    if (row >= NM_PAD) return;
    __nv_bfloat162* dst = (__nv_bfloat162*)(g_mbB + (size_t)row * D_);
    if (row < NM) {
        const float4* r = (const float4*)(mb + (size_t)row * D_);
        float4 v[6]; float s = 0.0f;
        #pragma unroll
        for (int i = 0; i < 6; i++) {
            v[i] = r[lane + i * 32];
            s += v[i].x * v[i].x + v[i].y * v[i].y + v[i].z * v[i].z + v[i].w * v[i].w;
        }
        #pragma unroll
        for (int o = 16; o; o >>= 1) s += __shfl_xor_sync(0xFFFFFFFFu, s, o);
        #pragma unroll
        for (int i = 0; i < 6; i++) {
            int e2 = (lane + i * 32) * 2;
            dst[e2]     = __floats2bfloat162_rn(v[i].x, v[i].y);
            dst[e2 + 1] = __floats2bfloat162_rn(v[i].z, v[i].w);
        }
        if (lane == 0) {
            float inv = 1.0f / (sqrtf(s) + 1e-12f);
            g_inv[row]  = inv;
            g_bias[row] = 0.5f * s * inv * inv;
        }
    } else {
        __nv_bfloat162 z = __floats2bfloat162_rn(0.f, 0.f);
        #pragma unroll
        for (int i = 0; i < 6; i++) {
            int e2 = (lane + i * 32) * 2;
            dst[e2] = z; dst[e2 + 1] = z;
        }
        if (lane == 0) { g_inv[row] = 0.0f; g_bias[row] = 1e30f; }
    }
}

// ---------------- kernel 3: init per-patch max ------------------------------
__global__ void init_max_kernel() {
    int i = blockIdx.x * blockDim.x + threadIdx.x;
    if (i < NP) g_maxv[i] = INT_MIN;
}

// ---------------- kernel 4: HMMA GEMM + max epilogue ------------------------
__global__ void __launch_bounds__(NTHR, 2)
gemm_mma_kernel() {
    extern __shared__ __align__(1024) char smem[];
    const uint32_t sbase = smem_u32(smem);
    const int tid  = threadIdx.x;
    const int wid  = tid >> 5;
    const int lane = tid & 31;
    const int p0 = blockIdx.x * BM;        // ptile fastest -> B-tile L2 reuse
    const int n0 = blockIdx.y * BN;

    const int wm = (wid & 1) * 64;         // warp M offset (0/64)
    const int wn_idx = wid >> 1;           // 0..3
    const int wn = wn_idx * 32;            // warp N offset

    float* inv_s  = (float*)(smem + SM_INV);
    float* bias_s = (float*)(smem + SM_BIAS);
    float* red    = (float*)(smem + SM_RED);

    if (tid < BN) {
        inv_s[tid]  = g_inv[n0 + tid];
        bias_s[tid] = g_bias[n0 + tid];
    }

    const __nv_bfloat16* gA = g_pA  + (size_t)p0 * D_;
    const __nv_bfloat16* gB = g_mbB + (size_t)n0 * D_;

    // cp.async indexing: tile = 128 rows x 64 cols bf16 = 1024 x 16B chunks
    const int ld_row = tid >> 3;           // 0..31 base row (x4 iters -> 128)
    const int ld_c   = tid & 7;            // 16B chunk in row

    // prologue: stage 0 <- chunk 0
    #pragma unroll
    for (int it = 0; it < 4; it++) {
        int row = ld_row + it * 32;
        uint32_t off = sw128(row * 128 + ld_c * 16);
        cp_async16(sbase + SM_A0 + off, gA + (size_t)row * D_ + ld_c * 8);
        cp_async16(sbase + SM_B0 + off, gB + (size_t)row * D_ + ld_c * 8);
    }
    CP_COMMIT();

    // ldmatrix lane address components
    const uint32_t aRow = (uint32_t)(wm + (lane & 15)) * 128;
    const uint32_t aCol = (uint32_t)((lane >> 4) << 4);
    const uint32_t bRow = (uint32_t)(wn + (lane & 7) + ((lane >> 4) << 3)) * 128;
    const uint32_t bCol = (uint32_t)(((lane >> 3) & 1) << 4);

    float acc[4][4][4];
    #pragma unroll
    for (int i = 0; i < 4; i++)
        #pragma unroll
        for (int j = 0; j < 4; j++)
            #pragma unroll
            for (int q = 0; q < 4; q++) acc[i][j][q] = 0.0f;

    #pragma unroll 1
    for (int kc = 0; kc < NCHUNK; kc++) {
        const int s = kc & 1;
        const uint32_t sA = sbase + (s ? SM_A1 : SM_A0);
        const uint32_t sB = sbase + (s ? SM_B1 : SM_B0);

        if (kc + 1 < NCHUNK) {
            const uint32_t dA = sbase + (s ? SM_A0 : SM_A1);
            const uint32_t dB = sbase + (s ? SM_B0 : SM_B1);
            const __nv_bfloat16* cA = gA + (size_t)(kc + 1) * KC;
            const __nv_bfloat16* cB = gB + (size_t)(kc + 1) * KC;
            #pragma unroll
            for (int it = 0; it < 4; it++) {
                int row = ld_row + it * 32;
                uint32_t off = sw128(row * 128 + ld_c * 16);
                cp_async16(dA + off, cA + (size_t)row * D_ + ld_c * 8);
                cp_async16(dB + off, cB + (size_t)row * D_ + ld_c * 8);
            }
            CP_COMMIT();
            CP_WAIT1();
        } else {
            CP_WAIT0();
        }
        __syncthreads();

        #pragma unroll
        for (int ks = 0; ks < 4; ks++) {
            const uint32_t kb = (uint32_t)(ks * 32);
            uint32_t af[4][4], bf[2][4];
            #pragma unroll
            for (int tm = 0; tm < 4; tm++)
                ldmat_x4(af[tm], sA + sw128(aRow + (uint32_t)(tm * 16 * 128) + kb + aCol));
            #pragma unroll
            for (int bn = 0; bn < 2; bn++)
                ldmat_x4(bf[bn], sB + sw128(bRow + (uint32_t)(bn * 16 * 128) + kb + bCol));
            #pragma unroll
            for (int tm = 0; tm < 4; tm++) {
                #pragma unroll
                for (int tn = 0; tn < 4; tn++)
                    mma16816(acc[tm][tn], af[tm], bf[tn >> 1] + (tn & 1) * 2);
            }
        }
        __syncthreads();
    }

    // ---- epilogue: v = dot*inv - bias, per-row max ----
    const int g  = lane >> 2;
    const int tq = lane & 3;
    #pragma unroll
    for (int tm = 0; tm < 4; tm++) {
        float b0 = -3.0e38f, b1 = -3.0e38f;
        #pragma unroll
        for (int tn = 0; tn < 4; tn++) {
            int c = wn + tn * 8 + 2 * tq;
            float i0 = inv_s[c], i1 = inv_s[c + 1];
            float s0 = bias_s[c], s1 = bias_s[c + 1];
            b0 = fmaxf(b0, fmaxf(acc[tm][tn][0] * i0 - s0, acc[tm][tn][1] * i1 - s1));
            b1 = fmaxf(b1, fmaxf(acc[tm][tn][2] * i0 - s0, acc[tm][tn][3] * i1 - s1));
        }
        b0 = fmaxf(b0, __shfl_xor_sync(0xFFFFFFFFu, b0, 1));
        b0 = fmaxf(b0, __shfl_xor_sync(0xFFFFFFFFu, b0, 2));
        b1 = fmaxf(b1, __shfl_xor_sync(0xFFFFFFFFu, b1, 1));
        b1 = fmaxf(b1, __shfl_xor_sync(0xFFFFFFFFu, b1, 2));
        if (tq == 0) {
            int r0 = wm + tm * 16 + g;
            red[r0 * 4 + wn_idx]       = b0;
            red[(r0 + 8) * 4 + wn_idx] = b1;
        }
    }
    __syncthreads();

    if (tid < BM) {
        float v = fmaxf(fmaxf(red[tid * 4], red[tid * 4 + 1]),
                        fmaxf(red[tid * 4 + 2], red[tid * 4 + 3]));
        int p = p0 + tid;
        if (p < NP) atomicMax(&g_maxv[p], f2ord(v));
    }
}

// ---------------- kernel 5: finalize per-image score ------------------------
__global__ void finalize_kernel(float* __restrict__ out) {
    int b = threadIdx.x;
    if (b >= B_) return;
    float mx = -3.0e38f;
    #pragma unroll 7
    for (int j = 0; j < P_PER_B; j++) {
        int p = b * P_PER_B + j;
        float v  = ord2f(g_maxv[p]);
        float d2 = g_p2[p] - 2.0f * v;
        mx = fmaxf(mx, d2);
    }
    out[b] = sqrtf(fmaxf(mx, 1e-12f));
}

// ---------------- launch -----------------------------------------------------
extern "C" void kernel_launch(void* const* d_in, const int* in_sizes, int n_in,
                              void* d_out, int out_size) {
    (void)in_sizes; (void)n_in; (void)out_size;
    const float* tokens = (const float*)d_in[0];
    const float* mb     = (const float*)d_in[1];
    float* out          = (float*)d_out;

    norm_patches_kernel<<<NP_PAD, 256>>>(tokens);
    mb_convert_kernel<<<NM_PAD / 8, 256>>>(mb);
    init_max_kernel<<<(NP + 255) / 256, 256>>>();

    cudaFuncSetAttribute(gemm_mma_kernel,
                         cudaFuncAttributeMaxDynamicSharedMemorySize, SM_TOTAL);
    dim3 grid(NP_PAD / BM, NM_PAD / BN);   // (25, 782)
    gemm_mma_kernel<<<grid, NTHR, SM_TOTAL>>>();

    finalize_kernel<<<1, 64>>>(out);
}